// round 16
// baseline (speedup 1.0000x reference)
#include <cuda_runtime.h>
#include <cuda_bf16.h>
#include <cstdint>

// ---------------------------------------------------------------------------
// LSTM autoencoder, pipelined: encoder layers e1/e2/e3 run CONCURRENTLY in one
// 112-CTA kernel (skewed systolically by 1 step); same for decoder d1/d2/d3.
// Gates = [Whh | Wih] . [h_own ; y_producer] + bias, computed per step.
// Cross-CTA / cross-layer exchange: per-layer 8-deep rings of packed
// (epoch<<32 | float) words, volatile 16-byte pair access, SINGLE dependent
// volatile load per poll. ONE __syncthreads per step (parity-buffered red).
// NEW: own-h polls are timer-gated -- each lane spins locally (zero memory
// traffic) until half the EMA-observed step period has elapsed since its
// last detect, THEN tight-polls. Cuts poll traffic ~2x without delaying
// detection (L2 RT < period/2).
// ---------------------------------------------------------------------------

#define T_SEQ 8192
typedef unsigned long long ull;

__device__ float g_ys [T_SEQ * 512];         // d3 output rows
__device__ ull   g_ring[6][8][512];          // per-layer h rings
__device__ int   g_prog[6];                  // per-layer progress counters

// ---------------------------------------------------------------------------
__device__ __forceinline__ float tanh_a(float x) {
    float y;
    asm("tanh.approx.f32 %0, %1;" : "=f"(y) : "f"(x));
    return y;
}
__device__ __forceinline__ void fma2(ull& d, ull a, ull b) {
    asm("fma.rn.f32x2 %0, %1, %2, %0;" : "+l"(d) : "l"(a), "l"(b));
}
__device__ __forceinline__ float f32x2_sum(ull v) {
    return __uint_as_float((unsigned)v) + __uint_as_float((unsigned)(v >> 32));
}
__device__ __forceinline__ void ld_v2_vol(const ull* p, ull& v0, ull& v1) {
    asm volatile("ld.volatile.v2.u64 {%0, %1}, [%2];"
                 : "=l"(v0), "=l"(v1) : "l"(p) : "memory");
}
__device__ __forceinline__ void st_v2_vol(ull* p, ull v0, ull v1) {
    asm volatile("st.volatile.v2.u64 [%0], {%1, %2};"
                 :: "l"(p), "l"(v0), "l"(v1) : "memory");
}
__device__ __forceinline__ ull gtimer() {
    ull t;
    asm volatile("mov.u64 %0, %%globaltimer;" : "=l"(t));
    return t;
}

// ---------------------------------------------------------------------------
__global__ void reset_prog_kernel() {
    if (threadIdx.x < 6) g_prog[threadIdx.x] = 0;
}

// ---------------------------------------------------------------------------
// One LSTM layer step-loop, run by B = H/8 CTAs inside a fused kernel.
//   XGMODE 0: input via Wih matvec (bias const)  [warps NWH..15 poll producer]
//   XGMODE 1: scalar input x[t]: xval = x[t]*Wih[grow] + bias      [e1]
//   XGMODE 2: constant input row, prologue dot vs ring ZRING slot0 [d1]
// Epochs: h of step t published with epoch t+1 in slot (t+1)&7.
// Own-h poll at step t: epoch t, slot t&7. Producer y_t: epoch t+1.
// Back-pressure: before finishing step t, wait g_prog[CONS] >= t-5 (ring 8).
// ---------------------------------------------------------------------------
template <int H, int HIN, int NWH, int XGMODE, int OWN, int PROD, int CONS,
          bool WRITE_YS, int ZRING = 0>
__device__ __forceinline__ void run_layer(
        int b,
        const float* __restrict__ Whh,
        const float* __restrict__ Wih,
        const float* __restrict__ bih,
        const float* __restrict__ bhh,
        const float* __restrict__ xs) {
    constexpr int NWI  = 16 - NWH;
    constexpr int SL_H = H / NWH;
    constexpr int SL_I = (HIN > 0) ? (HIN / (NWI > 0 ? NWI : 1)) : 2;
    constexpr int NQH  = SL_H / 2;
    constexpr int NQI  = (HIN > 0) ? SL_I / 2 : 0;
    constexpr int NQMAX = (NQI > NQH) ? NQI : NQH;

    const int tid  = threadIdx.x;
    const int wid  = tid >> 5;
    const int lane = tid & 31;
    const int gate = lane >> 3;
    const int unit = lane & 7;
    const int grow = gate * H + b * 8 + unit;
    const bool is_h = (wid < NWH);

    // weights in registers (f32x2 packed)
    ull wq[NQMAX];
    if (is_h) {
        const ull* wp = (const ull*)(Whh + (size_t)grow * H + wid * SL_H);
#pragma unroll
        for (int i = 0; i < NQH; ++i) wq[i] = wp[i];
    } else {
        if constexpr (HIN > 0) {
            const ull* wp = (const ull*)
                (Wih + (size_t)grow * HIN + (wid - NWH) * SL_I);
#pragma unroll
            for (int i = 0; i < NQI; ++i) wq[i] = wp[i];
        }
    }

    __shared__ __align__(16) float h_s[H + ((HIN > 0) ? HIN : 0)];
    __shared__ float red[2][16][32];    // parity double-buffered partials

    float c = 0.0f;
    float xconst = 0.0f;   // bias (mode 0/1) or full const input row (mode 2)
    float xw = 0.0f;       // e1 scalar input weight
    if (wid == 0) {
        if constexpr (XGMODE == 0) {
            xconst = bih[grow] + bhh[grow];
        } else if constexpr (XGMODE == 1) {
            xconst = bih[grow] + bhh[grow];
            xw = Wih[grow];                      // Wih is [4H, 1]
        } else {
            // prologue dot: xconst = b + Wih[grow,:] . z  (z = ring ZRING slot0)
            float s = bih[grow] + bhh[grow];
            const float* w = Wih + (size_t)grow * 128;
#pragma unroll 8
            for (int k = 0; k < 128; ++k) {
                float z = __uint_as_float(
                    (unsigned)*(volatile ull*)&g_ring[ZRING][0][k]);
                s += z * w[k];
            }
            xconst = s;
        }
    }

    // publish h0 = 0 with epoch 0 into slot 0 (16B pair stores)
    if (wid == 0 && lane < 8 && (lane & 1) == 0) {
        st_v2_vol(&g_ring[OWN][0][b * 8 + lane], 0ull, 0ull);
    }

    // timer-gated poll state (per own-h polling lane)
    ull last_d = 0;        // globaltimer at last detect (ns)
    unsigned p_ema = 0;    // EMA of step period (ns); 0 = not calibrated

    for (int t = 0; t < T_SEQ; ++t) {
        float xval = xconst;
        if (wid == 0) {
            if constexpr (XGMODE == 1)
                xval = fmaf(__ldg(xs + t), xw, xconst);
        }

        // back-pressure on consumer layer progress (ring depth 8)
        if constexpr (CONS >= 0) {
            if (wid == 15 && lane == 31) {
                volatile int* pp = &g_prog[CONS];
                while (*pp < t - 5) { __nanosleep(100); }
            }
        }

        // poll + stage this warp's slice (16B vector polls: 2 words/lane).
        if (is_h) {
            // own-h: timer-gated tight vector poll (critical cycle)
            if (lane < SL_H / 2) {
                const int base = wid * SL_H + 2 * lane;
                const ull* src = &g_ring[OWN][t & 7][base];
                // local spin (no memory traffic) until half the observed
                // period has elapsed since the last detect; L2 RT < P/2,
                // so this cannot delay detection.
                if (p_ema > 0) {
                    ull tgt = last_d + (ull)(p_ema >> 1);
                    while (gtimer() < tgt) { }
                }
                ull v0, v1;
                for (;;) {
                    ld_v2_vol(src, v0, v1);
                    if ((unsigned)(v0 >> 32) == (unsigned)t &&
                        (unsigned)(v1 >> 32) == (unsigned)t) break;
                }
                h_s[base]     = __uint_as_float((unsigned)v0);
                h_s[base + 1] = __uint_as_float((unsigned)v1);
                // update period EMA (off the h_s->matvec dependency)
                ull d = gtimer();
                if (last_d != 0) {
                    unsigned obs = (unsigned)(d - last_d);
                    if (obs > 4000u) obs = 4000u;
                    p_ema = p_ema
                        ? (unsigned)((int)p_ema + ((int)obs - (int)p_ema) / 8)
                        : obs;
                }
                last_d = d;
            }
        } else {
            if constexpr (HIN > 0) {
                // producer input: backoff vector poll (off critical cycle)
                if (lane < SL_I / 2) {
                    const int base = (wid - NWH) * SL_I + 2 * lane;
                    const ull* src = &g_ring[PROD][(t + 1) & 7][base];
                    ull v0, v1;
                    ld_v2_vol(src, v0, v1);
                    while ((unsigned)(v0 >> 32) != (unsigned)(t + 1) ||
                           (unsigned)(v1 >> 32) != (unsigned)(t + 1)) {
                        __nanosleep(40);
                        ld_v2_vol(src, v0, v1);
                    }
                    h_s[H + base]     = __uint_as_float((unsigned)v0);
                    h_s[H + base + 1] = __uint_as_float((unsigned)v1);
                }
            }
        }
        __syncwarp(0xffffffffu);   // staged slice visible to this warp

        // matvec partial over this warp's slice
        float part = 0.0f;
        if (is_h) {
            const ull* hq = (const ull*)&h_s[wid * SL_H];
            ull a0 = 0ull, a1 = 0ull;
#pragma unroll
            for (int i = 0; i < NQH; i += 2) {
                fma2(a0, wq[i], hq[i]);
                if (i + 1 < NQH) fma2(a1, wq[i + 1], hq[i + 1]);
            }
            part = f32x2_sum(a0) + f32x2_sum(a1);
        } else {
            if constexpr (HIN > 0) {
                const ull* hq = (const ull*)&h_s[H + (wid - NWH) * SL_I];
                ull a0 = 0ull, a1 = 0ull;
#pragma unroll
                for (int i = 0; i < NQI; i += 2) {
                    fma2(a0, wq[i], hq[i]);
                    if (i + 1 < NQI) fma2(a1, wq[i + 1], hq[i + 1]);
                }
                part = f32x2_sum(a0) + f32x2_sum(a1);
            }
        }
        red[t & 1][wid][lane] = part;
        __syncthreads();   // single per-step barrier: red[t&1] complete.

        if (wid == 0) {
            float s0 = xval, s1 = 0.0f, s2 = 0.0f, s3 = 0.0f;
            const float (*rp)[32] = red[t & 1];
#pragma unroll
            for (int k = 0; k < 16; k += 4) {
                s0 += rp[k][lane];
                s1 += rp[k + 1][lane];
                s2 += rp[k + 2][lane];
                s3 += rp[k + 3][lane];
            }
            float s = (s0 + s1) + (s2 + s3);

            // gate 2: tanh(s); others: sigmoid(s) = 0.5*tanh(0.5 s) + 0.5
            bool isg = (gate == 2);
            float sa = isg ? s : 0.5f * s;
            float tv = tanh_a(sa);
            float act = isg ? tv : fmaf(0.5f, tv, 0.5f);

            float i_ = __shfl_sync(0xffffffffu, act, unit);
            float f_ = __shfl_sync(0xffffffffu, act, 8 + unit);
            float g_ = __shfl_sync(0xffffffffu, act, 16 + unit);
            float o_ = __shfl_sync(0xffffffffu, act, 24 + unit);

            // compute unconditionally (lanes >= 8 produce unused duplicates)
            c = f_ * c + i_ * g_;
            float h = o_ * tanh_a(c);
            ull word = (((ull)(unsigned)(t + 1)) << 32)
                     | (ull)__float_as_uint(h);
            ull word2 = __shfl_down_sync(0xffffffffu, word, 1);
            if (lane < 8) {
                if ((lane & 1) == 0) {
                    st_v2_vol(&g_ring[OWN][(t + 1) & 7][b * 8 + lane],
                              word, word2);
                }
                if (WRITE_YS)
                    g_ys[(size_t)t * 512 + b * 8 + lane] = h;
            }
            if (b == 0 && lane == 8) {
                *(volatile int*)&g_prog[OWN] = t + 1;
            }
        }
        // non-warp-0 warps run ahead into the next step's poll while warp 0
        // finishes the tail; they stall at barrier(t+1) until warp 0 arrives.
    }
}

// ---------------------------------------------------------------------------
// Fused encoder: e1 (64 CTAs), e2 (32), e3 (16) -- 112 CTAs, single wave.
// ---------------------------------------------------------------------------
__global__ void __launch_bounds__(512, 1) encoder_kernel(
        const float* __restrict__ x,
        const float* __restrict__ e1_Whh, const float* __restrict__ e1_Wih,
        const float* __restrict__ e1_bih, const float* __restrict__ e1_bhh,
        const float* __restrict__ e2_Whh, const float* __restrict__ e2_Wih,
        const float* __restrict__ e2_bih, const float* __restrict__ e2_bhh,
        const float* __restrict__ e3_Whh, const float* __restrict__ e3_Wih,
        const float* __restrict__ e3_bih, const float* __restrict__ e3_bhh) {
    int bx = blockIdx.x;
    if (bx < 64) {
        run_layer<512, 0, 16, /*XG*/1, /*OWN*/0, /*PROD*/0, /*CONS*/1, false>(
            bx, e1_Whh, e1_Wih, e1_bih, e1_bhh, x);
    } else if (bx < 96) {
        run_layer<256, 512, 8, 0, 1, 0, 2, false>(
            bx - 64, e2_Whh, e2_Wih, e2_bih, e2_bhh, nullptr);
    } else {
        run_layer<128, 256, 8, 0, 2, 1, -1, false>(
            bx - 96, e3_Whh, e3_Wih, e3_bih, e3_bhh, nullptr);
    }
}

// ---------------------------------------------------------------------------
// Fused decoder: d1 (16 CTAs), d2 (32), d3 (64) -- 112 CTAs, single wave.
// ---------------------------------------------------------------------------
__global__ void __launch_bounds__(512, 1) decoder_kernel(
        const float* __restrict__ d1_Whh, const float* __restrict__ d1_Wih,
        const float* __restrict__ d1_bih, const float* __restrict__ d1_bhh,
        const float* __restrict__ d2_Whh, const float* __restrict__ d2_Wih,
        const float* __restrict__ d2_bih, const float* __restrict__ d2_bhh,
        const float* __restrict__ d3_Whh, const float* __restrict__ d3_Wih,
        const float* __restrict__ d3_bih, const float* __restrict__ d3_bhh) {
    int bx = blockIdx.x;
    if (bx < 16) {
        // d1: constant input row from e3's final h (ring 2, slot 0)
        run_layer<128, 0, 16, /*XG*/2, /*OWN*/3, /*PROD*/3, /*CONS*/4, false,
                  /*ZRING*/2>(
            bx, d1_Whh, d1_Wih, d1_bih, d1_bhh, nullptr);
    } else if (bx < 48) {
        run_layer<256, 128, 8, 0, 4, 3, 5, false>(
            bx - 16, d2_Whh, d2_Wih, d2_bih, d2_bhh, nullptr);
    } else {
        run_layer<512, 256, 8, 0, 5, 4, -1, true>(
            bx - 48, d3_Whh, d3_Wih, d3_bih, d3_bhh, nullptr);
    }
}

// ---------------------------------------------------------------------------
// Final projection: out[t] = ys_d3[t,:] . out_W + out_b
// ---------------------------------------------------------------------------
__global__ void out_proj_kernel(const float* __restrict__ w,
                                const float* __restrict__ bias,
                                float* __restrict__ out) {
    int gtid = blockIdx.x * blockDim.x + threadIdx.x;
    int warp = gtid >> 5;
    int lane = threadIdx.x & 31;
    if (warp >= T_SEQ) return;
    const float* y = g_ys + (size_t)warp * 512;
    float s = 0.0f;
#pragma unroll
    for (int j = 0; j < 16; ++j) {
        s += y[lane + 32 * j] * w[lane + 32 * j];
    }
#pragma unroll
    for (int off = 16; off > 0; off >>= 1)
        s += __shfl_down_sync(0xffffffffu, s, off);
    if (lane == 0) out[warp] = s + bias[0];
}

// ---------------------------------------------------------------------------
extern "C" void kernel_launch(void* const* d_in, const int* in_sizes, int n_in,
                              void* d_out, int out_size) {
    const float* x       = (const float*)d_in[0];
    const float* e1_Wih  = (const float*)d_in[1];
    const float* e1_Whh  = (const float*)d_in[2];
    const float* e1_bih  = (const float*)d_in[3];
    const float* e1_bhh  = (const float*)d_in[4];
    const float* e2_Wih  = (const float*)d_in[5];
    const float* e2_Whh  = (const float*)d_in[6];
    const float* e2_bih  = (const float*)d_in[7];
    const float* e2_bhh  = (const float*)d_in[8];
    const float* e3_Wih  = (const float*)d_in[9];
    const float* e3_Whh  = (const float*)d_in[10];
    const float* e3_bih  = (const float*)d_in[11];
    const float* e3_bhh  = (const float*)d_in[12];
    const float* d1_Wih  = (const float*)d_in[13];
    const float* d1_Whh  = (const float*)d_in[14];
    const float* d1_bih  = (const float*)d_in[15];
    const float* d1_bhh  = (const float*)d_in[16];
    const float* d2_Wih  = (const float*)d_in[17];
    const float* d2_Whh  = (const float*)d_in[18];
    const float* d2_bih  = (const float*)d_in[19];
    const float* d2_bhh  = (const float*)d_in[20];
    const float* d3_Wih  = (const float*)d_in[21];
    const float* d3_Whh  = (const float*)d_in[22];
    const float* d3_bih  = (const float*)d_in[23];
    const float* d3_bhh  = (const float*)d_in[24];
    const float* out_W   = (const float*)d_in[25];
    const float* out_b   = (const float*)d_in[26];
    float* out = (float*)d_out;

    reset_prog_kernel<<<1, 32>>>();

    encoder_kernel<<<112, 512>>>(x,
                                 e1_Whh, e1_Wih, e1_bih, e1_bhh,
                                 e2_Whh, e2_Wih, e2_bih, e2_bhh,
                                 e3_Whh, e3_Wih, e3_bih, e3_bhh);

    decoder_kernel<<<112, 512>>>(d1_Whh, d1_Wih, d1_bih, d1_bhh,
                                 d2_Whh, d2_Wih, d2_bih, d2_bhh,
                                 d3_Whh, d3_Wih, d3_bih, d3_bhh);

    out_proj_kernel<<<(T_SEQ * 32) / 256, 256>>>(out_W, out_b, out);
}

// round 17
// speedup vs baseline: 1.0482x; 1.0482x over previous
#include <cuda_runtime.h>
#include <cuda_bf16.h>
#include <cstdint>

// ---------------------------------------------------------------------------
// LSTM autoencoder, pipelined: encoder layers e1/e2/e3 run CONCURRENTLY in one
// 112-CTA kernel (skewed systolically by 1 step); same for decoder d1/d2/d3.
// Gates = [Whh | Wih] . [h_own ; y_producer] + bias, computed per step.
// Cross-CTA / cross-layer exchange: per-layer 8-deep rings of packed
// (epoch<<32 | float) words, volatile 16-byte pair access, SINGLE dependent
// volatile load per poll (proven optimal). ONE __syncthreads per step
// (parity double-buffered red). Input polls are now TIGHT dependent loops
// (no nanosleep) -- removes coarse sleep jitter from the consumer layers'
// per-step barrier max.
// ---------------------------------------------------------------------------

#define T_SEQ 8192
typedef unsigned long long ull;

__device__ float g_ys [T_SEQ * 512];         // d3 output rows
__device__ ull   g_ring[6][8][512];          // per-layer h rings
__device__ int   g_prog[6];                  // per-layer progress counters

// ---------------------------------------------------------------------------
__device__ __forceinline__ float tanh_a(float x) {
    float y;
    asm("tanh.approx.f32 %0, %1;" : "=f"(y) : "f"(x));
    return y;
}
__device__ __forceinline__ void fma2(ull& d, ull a, ull b) {
    asm("fma.rn.f32x2 %0, %1, %2, %0;" : "+l"(d) : "l"(a), "l"(b));
}
__device__ __forceinline__ float f32x2_sum(ull v) {
    return __uint_as_float((unsigned)v) + __uint_as_float((unsigned)(v >> 32));
}
__device__ __forceinline__ void ld_v2_vol(const ull* p, ull& v0, ull& v1) {
    asm volatile("ld.volatile.v2.u64 {%0, %1}, [%2];"
                 : "=l"(v0), "=l"(v1) : "l"(p) : "memory");
}
__device__ __forceinline__ void st_v2_vol(ull* p, ull v0, ull v1) {
    asm volatile("st.volatile.v2.u64 [%0], {%1, %2};"
                 :: "l"(p), "l"(v0), "l"(v1) : "memory");
}

// ---------------------------------------------------------------------------
__global__ void reset_prog_kernel() {
    if (threadIdx.x < 6) g_prog[threadIdx.x] = 0;
}

// ---------------------------------------------------------------------------
// One LSTM layer step-loop, run by B = H/8 CTAs inside a fused kernel.
//   XGMODE 0: input via Wih matvec (bias const)  [warps NWH..15 poll producer]
//   XGMODE 1: scalar input x[t]: xval = x[t]*Wih[grow] + bias      [e1]
//   XGMODE 2: constant input row, prologue dot vs ring ZRING slot0 [d1]
// Epochs: h of step t published with epoch t+1 in slot (t+1)&7.
// Own-h poll at step t: epoch t, slot t&7. Producer y_t: epoch t+1.
// Back-pressure: before finishing step t, wait g_prog[CONS] >= t-5 (ring 8).
// ---------------------------------------------------------------------------
template <int H, int HIN, int NWH, int XGMODE, int OWN, int PROD, int CONS,
          bool WRITE_YS, int ZRING = 0>
__device__ __forceinline__ void run_layer(
        int b,
        const float* __restrict__ Whh,
        const float* __restrict__ Wih,
        const float* __restrict__ bih,
        const float* __restrict__ bhh,
        const float* __restrict__ xs) {
    constexpr int NWI  = 16 - NWH;
    constexpr int SL_H = H / NWH;
    constexpr int SL_I = (HIN > 0) ? (HIN / (NWI > 0 ? NWI : 1)) : 2;
    constexpr int NQH  = SL_H / 2;
    constexpr int NQI  = (HIN > 0) ? SL_I / 2 : 0;
    constexpr int NQMAX = (NQI > NQH) ? NQI : NQH;

    const int tid  = threadIdx.x;
    const int wid  = tid >> 5;
    const int lane = tid & 31;
    const int gate = lane >> 3;
    const int unit = lane & 7;
    const int grow = gate * H + b * 8 + unit;
    const bool is_h = (wid < NWH);

    // weights in registers (f32x2 packed)
    ull wq[NQMAX];
    if (is_h) {
        const ull* wp = (const ull*)(Whh + (size_t)grow * H + wid * SL_H);
#pragma unroll
        for (int i = 0; i < NQH; ++i) wq[i] = wp[i];
    } else {
        if constexpr (HIN > 0) {
            const ull* wp = (const ull*)
                (Wih + (size_t)grow * HIN + (wid - NWH) * SL_I);
#pragma unroll
            for (int i = 0; i < NQI; ++i) wq[i] = wp[i];
        }
    }

    __shared__ __align__(16) float h_s[H + ((HIN > 0) ? HIN : 0)];
    __shared__ float red[2][16][32];    // parity double-buffered partials

    float c = 0.0f;
    float xconst = 0.0f;   // bias (mode 0/1) or full const input row (mode 2)
    float xw = 0.0f;       // e1 scalar input weight
    if (wid == 0) {
        if constexpr (XGMODE == 0) {
            xconst = bih[grow] + bhh[grow];
        } else if constexpr (XGMODE == 1) {
            xconst = bih[grow] + bhh[grow];
            xw = Wih[grow];                      // Wih is [4H, 1]
        } else {
            // prologue dot: xconst = b + Wih[grow,:] . z  (z = ring ZRING slot0)
            float s = bih[grow] + bhh[grow];
            const float* w = Wih + (size_t)grow * 128;
#pragma unroll 8
            for (int k = 0; k < 128; ++k) {
                float z = __uint_as_float(
                    (unsigned)*(volatile ull*)&g_ring[ZRING][0][k]);
                s += z * w[k];
            }
            xconst = s;
        }
    }

    // publish h0 = 0 with epoch 0 into slot 0 (16B pair stores)
    if (wid == 0 && lane < 8 && (lane & 1) == 0) {
        st_v2_vol(&g_ring[OWN][0][b * 8 + lane], 0ull, 0ull);
    }

    for (int t = 0; t < T_SEQ; ++t) {
        float xval = xconst;
        if (wid == 0) {
            if constexpr (XGMODE == 1)
                xval = fmaf(__ldg(xs + t), xw, xconst);
        }

        // back-pressure on consumer layer progress (ring depth 8)
        if constexpr (CONS >= 0) {
            if (wid == 15 && lane == 31) {
                volatile int* pp = &g_prog[CONS];
                while (*pp < t - 5) { __nanosleep(100); }
            }
        }

        // poll + stage this warp's slice (16B vector polls: 2 words/lane).
        // Staging is warp-local: this warp's matvec reads exactly the slice
        // its own lanes stage, so only __syncwarp is needed.
        if (is_h) {
            // own-h: tight vector poll (critical cycle), single load/probe
            if (lane < SL_H / 2) {
                const int base = wid * SL_H + 2 * lane;
                const ull* src = &g_ring[OWN][t & 7][base];
                ull v0, v1;
                for (;;) {
                    ld_v2_vol(src, v0, v1);
                    if ((unsigned)(v0 >> 32) == (unsigned)t &&
                        (unsigned)(v1 >> 32) == (unsigned)t) break;
                }
                h_s[base]     = __uint_as_float((unsigned)v0);
                h_s[base + 1] = __uint_as_float((unsigned)v1);
            }
        } else {
            if constexpr (HIN > 0) {
                // producer input: tight vector poll (no nanosleep jitter)
                if (lane < SL_I / 2) {
                    const int base = (wid - NWH) * SL_I + 2 * lane;
                    const ull* src = &g_ring[PROD][(t + 1) & 7][base];
                    ull v0, v1;
                    for (;;) {
                        ld_v2_vol(src, v0, v1);
                        if ((unsigned)(v0 >> 32) == (unsigned)(t + 1) &&
                            (unsigned)(v1 >> 32) == (unsigned)(t + 1)) break;
                    }
                    h_s[H + base]     = __uint_as_float((unsigned)v0);
                    h_s[H + base + 1] = __uint_as_float((unsigned)v1);
                }
            }
        }
        __syncwarp(0xffffffffu);   // staged slice visible to this warp

        // matvec partial over this warp's slice
        float part = 0.0f;
        if (is_h) {
            const ull* hq = (const ull*)&h_s[wid * SL_H];
            ull a0 = 0ull, a1 = 0ull;
#pragma unroll
            for (int i = 0; i < NQH; i += 2) {
                fma2(a0, wq[i], hq[i]);
                if (i + 1 < NQH) fma2(a1, wq[i + 1], hq[i + 1]);
            }
            part = f32x2_sum(a0) + f32x2_sum(a1);
        } else {
            if constexpr (HIN > 0) {
                const ull* hq = (const ull*)&h_s[H + (wid - NWH) * SL_I];
                ull a0 = 0ull, a1 = 0ull;
#pragma unroll
                for (int i = 0; i < NQI; i += 2) {
                    fma2(a0, wq[i], hq[i]);
                    if (i + 1 < NQI) fma2(a1, wq[i + 1], hq[i + 1]);
                }
                part = f32x2_sum(a0) + f32x2_sum(a1);
            }
        }
        red[t & 1][wid][lane] = part;
        __syncthreads();   // single per-step barrier: red[t&1] complete.
        // red[t&1] cannot be overwritten (step t+2) until every warp passes
        // barrier(t+1), which warp 0 reaches only AFTER reading red[t&1].

        if (wid == 0) {
            float s0 = xval, s1 = 0.0f, s2 = 0.0f, s3 = 0.0f;
            const float (*rp)[32] = red[t & 1];
#pragma unroll
            for (int k = 0; k < 16; k += 4) {
                s0 += rp[k][lane];
                s1 += rp[k + 1][lane];
                s2 += rp[k + 2][lane];
                s3 += rp[k + 3][lane];
            }
            float s = (s0 + s1) + (s2 + s3);

            // gate 2: tanh(s); others: sigmoid(s) = 0.5*tanh(0.5 s) + 0.5
            bool isg = (gate == 2);
            float sa = isg ? s : 0.5f * s;
            float tv = tanh_a(sa);
            float act = isg ? tv : fmaf(0.5f, tv, 0.5f);

            float i_ = __shfl_sync(0xffffffffu, act, unit);
            float f_ = __shfl_sync(0xffffffffu, act, 8 + unit);
            float g_ = __shfl_sync(0xffffffffu, act, 16 + unit);
            float o_ = __shfl_sync(0xffffffffu, act, 24 + unit);

            // compute unconditionally (lanes >= 8 produce unused duplicates)
            c = f_ * c + i_ * g_;
            float h = o_ * tanh_a(c);
            ull word = (((ull)(unsigned)(t + 1)) << 32)
                     | (ull)__float_as_uint(h);
            ull word2 = __shfl_down_sync(0xffffffffu, word, 1);
            if (lane < 8) {
                if ((lane & 1) == 0) {
                    st_v2_vol(&g_ring[OWN][(t + 1) & 7][b * 8 + lane],
                              word, word2);
                }
                if (WRITE_YS)
                    g_ys[(size_t)t * 512 + b * 8 + lane] = h;
            }
            if (b == 0 && lane == 8) {
                *(volatile int*)&g_prog[OWN] = t + 1;
            }
        }
        // non-warp-0 warps run ahead into the next step's poll while warp 0
        // finishes the tail; they stall at barrier(t+1) until warp 0 arrives.
    }
}

// ---------------------------------------------------------------------------
// Fused encoder: e1 (64 CTAs), e2 (32), e3 (16) -- 112 CTAs, single wave.
// ---------------------------------------------------------------------------
__global__ void __launch_bounds__(512, 1) encoder_kernel(
        const float* __restrict__ x,
        const float* __restrict__ e1_Whh, const float* __restrict__ e1_Wih,
        const float* __restrict__ e1_bih, const float* __restrict__ e1_bhh,
        const float* __restrict__ e2_Whh, const float* __restrict__ e2_Wih,
        const float* __restrict__ e2_bih, const float* __restrict__ e2_bhh,
        const float* __restrict__ e3_Whh, const float* __restrict__ e3_Wih,
        const float* __restrict__ e3_bih, const float* __restrict__ e3_bhh) {
    int bx = blockIdx.x;
    if (bx < 64) {
        run_layer<512, 0, 16, /*XG*/1, /*OWN*/0, /*PROD*/0, /*CONS*/1, false>(
            bx, e1_Whh, e1_Wih, e1_bih, e1_bhh, x);
    } else if (bx < 96) {
        run_layer<256, 512, 8, 0, 1, 0, 2, false>(
            bx - 64, e2_Whh, e2_Wih, e2_bih, e2_bhh, nullptr);
    } else {
        run_layer<128, 256, 8, 0, 2, 1, -1, false>(
            bx - 96, e3_Whh, e3_Wih, e3_bih, e3_bhh, nullptr);
    }
}

// ---------------------------------------------------------------------------
// Fused decoder: d1 (16 CTAs), d2 (32), d3 (64) -- 112 CTAs, single wave.
// ---------------------------------------------------------------------------
__global__ void __launch_bounds__(512, 1) decoder_kernel(
        const float* __restrict__ d1_Whh, const float* __restrict__ d1_Wih,
        const float* __restrict__ d1_bih, const float* __restrict__ d1_bhh,
        const float* __restrict__ d2_Whh, const float* __restrict__ d2_Wih,
        const float* __restrict__ d2_bih, const float* __restrict__ d2_bhh,
        const float* __restrict__ d3_Whh, const float* __restrict__ d3_Wih,
        const float* __restrict__ d3_bih, const float* __restrict__ d3_bhh) {
    int bx = blockIdx.x;
    if (bx < 16) {
        // d1: constant input row from e3's final h (ring 2, slot 0)
        run_layer<128, 0, 16, /*XG*/2, /*OWN*/3, /*PROD*/3, /*CONS*/4, false,
                  /*ZRING*/2>(
            bx, d1_Whh, d1_Wih, d1_bih, d1_bhh, nullptr);
    } else if (bx < 48) {
        run_layer<256, 128, 8, 0, 4, 3, 5, false>(
            bx - 16, d2_Whh, d2_Wih, d2_bih, d2_bhh, nullptr);
    } else {
        run_layer<512, 256, 8, 0, 5, 4, -1, true>(
            bx - 48, d3_Whh, d3_Wih, d3_bih, d3_bhh, nullptr);
    }
}

// ---------------------------------------------------------------------------
// Final projection: out[t] = ys_d3[t,:] . out_W + out_b
// ---------------------------------------------------------------------------
__global__ void out_proj_kernel(const float* __restrict__ w,
                                const float* __restrict__ bias,
                                float* __restrict__ out) {
    int gtid = blockIdx.x * blockDim.x + threadIdx.x;
    int warp = gtid >> 5;
    int lane = threadIdx.x & 31;
    if (warp >= T_SEQ) return;
    const float* y = g_ys + (size_t)warp * 512;
    float s = 0.0f;
#pragma unroll
    for (int j = 0; j < 16; ++j) {
        s += y[lane + 32 * j] * w[lane + 32 * j];
    }
#pragma unroll
    for (int off = 16; off > 0; off >>= 1)
        s += __shfl_down_sync(0xffffffffu, s, off);
    if (lane == 0) out[warp] = s + bias[0];
}

// ---------------------------------------------------------------------------
extern "C" void kernel_launch(void* const* d_in, const int* in_sizes, int n_in,
                              void* d_out, int out_size) {
    const float* x       = (const float*)d_in[0];
    const float* e1_Wih  = (const float*)d_in[1];
    const float* e1_Whh  = (const float*)d_in[2];
    const float* e1_bih  = (const float*)d_in[3];
    const float* e1_bhh  = (const float*)d_in[4];
    const float* e2_Wih  = (const float*)d_in[5];
    const float* e2_Whh  = (const float*)d_in[6];
    const float* e2_bih  = (const float*)d_in[7];
    const float* e2_bhh  = (const float*)d_in[8];
    const float* e3_Wih  = (const float*)d_in[9];
    const float* e3_Whh  = (const float*)d_in[10];
    const float* e3_bih  = (const float*)d_in[11];
    const float* e3_bhh  = (const float*)d_in[12];
    const float* d1_Wih  = (const float*)d_in[13];
    const float* d1_Whh  = (const float*)d_in[14];
    const float* d1_bih  = (const float*)d_in[15];
    const float* d1_bhh  = (const float*)d_in[16];
    const float* d2_Wih  = (const float*)d_in[17];
    const float* d2_Whh  = (const float*)d_in[18];
    const float* d2_bih  = (const float*)d_in[19];
    const float* d2_bhh  = (const float*)d_in[20];
    const float* d3_Wih  = (const float*)d_in[21];
    const float* d3_Whh  = (const float*)d_in[22];
    const float* d3_bih  = (const float*)d_in[23];
    const float* d3_bhh  = (const float*)d_in[24];
    const float* out_W   = (const float*)d_in[25];
    const float* out_b   = (const float*)d_in[26];
    float* out = (float*)d_out;

    reset_prog_kernel<<<1, 32>>>();

    encoder_kernel<<<112, 512>>>(x,
                                 e1_Whh, e1_Wih, e1_bih, e1_bhh,
                                 e2_Whh, e2_Wih, e2_bih, e2_bhh,
                                 e3_Whh, e3_Wih, e3_bih, e3_bhh);

    decoder_kernel<<<112, 512>>>(d1_Whh, d1_Wih, d1_bih, d1_bhh,
                                 d2_Whh, d2_Wih, d2_bih, d2_bhh,
                                 d3_Whh, d3_Wih, d3_bih, d3_bhh);

    out_proj_kernel<<<(T_SEQ * 32) / 256, 256>>>(out_W, out_b, out);
}